// round 10
// baseline (speedup 1.0000x reference)
#include <cuda_runtime.h>
#include <cstdint>

#define NIMG  8
#define NPROP 8000
#define NCLS  80
#define NLOG  81
#define KTOP  2048
#define CAP   4096
#define NDET  100
#define NW    32    // 2048 / 64 bits
#define SROWS 640   // suppression rows kept in smem (overflow -> g_sup)

#define SCORE_THRE 0.15f
#define MIN_AREA   0.1f
#define NMS_TH     0.5f

// dynamic smem layout for supscan: sbox | sarea | srows
#define SUPSCAN_SBOX_OFF  0
#define SUPSCAN_SAREA_OFF (KTOP * 16)                    // 32768
#define SUPSCAN_SROWS_OFF (SUPSCAN_SAREA_OFF + KTOP * 4) // 40960
#define SUPSCAN_SMEM      (SUPSCAN_SROWS_OFF + SROWS * NW * 8)  // 204800

// ---------------- scratch (device globals; no allocations allowed) ----------
__device__ int                 g_cnt[NIMG];
__device__ int                 g_ncand[NIMG];
__device__ unsigned long long  g_keys[NIMG][CAP];
__device__ float               g_box[NIMG][KTOP][4];
__device__ float               g_val[NIMG][KTOP];
__device__ int                 g_lab[NIMG][KTOP];
__device__ float               g_maxc[NIMG];
__device__ unsigned long long  g_sup[NIMG][KTOP][NW];   // overflow rows only

// ---------------- kernel 1: softmax + decode + filter + append --------------
__global__ void score_kernel(const float* __restrict__ logits,
                             const float* __restrict__ deltas,
                             const float* __restrict__ props) {
    int b    = blockIdx.y;
    int p    = blockIdx.x * (blockDim.x >> 5) + (threadIdx.x >> 5);
    int lane = threadIdx.x & 31;
    if (p >= NPROP) return;

    const float* lg = logits + (size_t)(b * NPROP + p) * NLOG;
    float v0 = lg[lane];
    float v1 = lg[32 + lane];
    float v2 = (lane < NLOG - 64) ? lg[64 + lane] : -3.4e38f;

    float mx = fmaxf(fmaxf(v0, v1), v2);
#pragma unroll
    for (int o = 16; o; o >>= 1) mx = fmaxf(mx, __shfl_xor_sync(0xffffffffu, mx, o));

    float e0 = expf(v0 - mx);
    float e1 = expf(v1 - mx);
    float e2 = (lane < NLOG - 64) ? expf(v2 - mx) : 0.0f;
    float s  = e0 + e1 + e2;
#pragma unroll
    for (int o = 16; o; o >>= 1) s += __shfl_xor_sync(0xffffffffu, s, o);

    float inv_s = (lane == 0) ? (1.0f / s) : 0.0f;   // one IEEE rcp per warp
    inv_s = __shfl_sync(0xffffffffu, inv_s, 0);

    const float* pr = props + (size_t)(b * NPROP + p) * 4;
    float wa = pr[2] - pr[0];
    float ha = pr[3] - pr[1];

    const float* dl = deltas + (size_t)(b * NPROP + p) * (4 * NLOG);

    float es[3] = { e0, e1, e2 };
#pragma unroll
    for (int t = 0; t < 3; t++) {
        int cls = lane + 32 * t;                 // softmax class index
        if (cls >= 1 && cls < NLOG) {
            float sc = es[t] * inv_s;
            if (sc > SCORE_THRE) {
                float dw = dl[4 * cls + 2];
                float dh = dl[4 * cls + 3];
                float w  = __expf(dw) * wa;      // area test only
                float h  = __expf(dh) * ha;
                float area = h * w;
                if (area > MIN_AREA) {
                    int idx = p * NCLS + (cls - 1);
                    int pos = atomicAdd(&g_cnt[b], 1);
                    if (pos < CAP) {
                        unsigned long long key =
                            ((unsigned long long)__float_as_uint(sc) << 32) |
                            (unsigned)(0xFFFFFFFFu - (unsigned)idx);
                        g_keys[b][pos] = key;
                    }
                }
            }
        }
    }
}

// ---------------- kernel 2: sort + gather fused (one block per image) -------
__global__ void sortgather_kernel(const float* __restrict__ deltas,
                                  const float* __restrict__ props) {
    __shared__ unsigned long long sk[CAP];
    __shared__ float smax[32];
    int b = blockIdx.x;
    int t = threadIdx.x;
    int cnt = g_cnt[b];
    if (cnt > CAP) cnt = CAP;

    int npow = 1024;
    while (npow < cnt) npow <<= 1;               // <= CAP

    for (int i = t; i < npow; i += 1024)
        sk[i] = (i < cnt) ? g_keys[b][i] : 0ull;
    __syncthreads();
    if (t == 0) {
        g_cnt[b]   = 0;                          // reset for next replay
        g_ncand[b] = (cnt < KTOP) ? cnt : KTOP;  // real candidate count
    }

    for (int k = 2; k <= npow; k <<= 1) {
        for (int j = k >> 1; j; j >>= 1) {
            for (int idx = t; idx < (npow >> 1); idx += 1024) {
                int low = idx & (j - 1);
                int i   = ((idx ^ low) << 1) | low;
                int ixj = i | j;
                unsigned long long a = sk[i], c = sk[ixj];
                bool up = ((i & k) == 0);
                if ((a > c) == up) { sk[i] = c; sk[ixj] = a; }
            }
            __syncthreads();
        }
    }

    // ---- gather phase: ranks r = t, t+1024 (KTOP = 2*1024) ----
    float m_loc = 0.0f;
#pragma unroll
    for (int rr = 0; rr < KTOP / 1024; rr++) {
        int r = t + rr * 1024;
        unsigned long long key = (r < npow) ? sk[npow - 1 - r] : 0ull;
        if (key == 0ull) {
            g_val[b][r] = -1.0f;
            g_lab[b][r] = 0;
            g_box[b][r][0] = 0.f; g_box[b][r][1] = 0.f;
            g_box[b][r][2] = 0.f; g_box[b][r][3] = 0.f;
        } else {
            float    sc  = __uint_as_float((unsigned)(key >> 32));
            unsigned idx = 0xFFFFFFFFu - (unsigned)(key & 0xFFFFFFFFull);
            int p   = (int)(idx / NCLS);
            int cls = (int)(idx - (unsigned)p * NCLS) + 1;

            const float* pr = props + (size_t)(b * NPROP + p) * 4;
            float ax0 = pr[0], ay0 = pr[1], ax1 = pr[2], ay1 = pr[3];
            float wa  = ax1 - ax0, ha = ay1 - ay0;
            float cxa = ax0 + 0.5f * wa, cya = ay0 + 0.5f * ha;

            const float* dl = deltas + (size_t)(b * NPROP + p) * (4 * NLOG);
            float dx = dl[4 * cls + 0];
            float dy = dl[4 * cls + 1];
            float dw = dl[4 * cls + 2];
            float dh = dl[4 * cls + 3];
            float cx = dx * wa + cxa;
            float cy = dy * ha + cya;
            float w  = expf(dw) * wa;
            float h  = expf(dh) * ha;
            float bx0 = cx - 0.5f * w, by0 = cy - 0.5f * h;
            float bx1 = cx + 0.5f * w, by1 = cy + 0.5f * h;

            g_box[b][r][0] = bx0; g_box[b][r][1] = by0;
            g_box[b][r][2] = bx1; g_box[b][r][3] = by1;
            g_val[b][r] = sc;
            g_lab[b][r] = cls;

            m_loc = fmaxf(m_loc, fmaxf(fmaxf(bx0, bx1), fmaxf(by0, by1)));
        }
    }

    // ---- block max reduction for max_coord ----
#pragma unroll
    for (int o = 16; o; o >>= 1)
        m_loc = fmaxf(m_loc, __shfl_xor_sync(0xffffffffu, m_loc, o));
    if ((t & 31) == 0) smax[t >> 5] = m_loc;
    __syncthreads();
    if (t < 32) {
        float m = smax[t];
#pragma unroll
        for (int o = 16; o; o >>= 1)
            m = fmaxf(m, __shfl_xor_sync(0xffffffffu, m, o));
        if (t == 0) g_maxc[b] = m;
    }
}

// ---------------- kernel 3: fused suppression + greedy NMS + output ---------
// one block per image; suppression matrix lives in dynamic smem (SROWS rows)
__global__ void supscan_kernel(float* __restrict__ out) {
    extern __shared__ char dynsmem[];
    float4*             sbox  = (float4*)(dynsmem + SUPSCAN_SBOX_OFF);
    float*              sarea = (float*)(dynsmem + SUPSCAN_SAREA_OFF);
    unsigned long long* srows = (unsigned long long*)(dynsmem + SUPSCAN_SROWS_OFF);
    __shared__ int kept[NDET];
    __shared__ int s_cnt;

    int b    = blockIdx.x;
    int tid  = threadIdx.x;
    int warp = tid >> 5;
    int lane = tid & 31;
    int ncand = g_ncand[b];
    float mc  = g_maxc[b] + 1.0f;

    // ---- stage offset boxes + areas ----
    for (int i = tid; i < ncand; i += 1024) {
        float4 bx = *(const float4*)&g_box[b][i][0];
        float off = (float)g_lab[b][i] * mc;
        bx.x += off; bx.y += off; bx.z += off; bx.w += off;
        sbox[i]  = bx;
        sarea[i] = (bx.z - bx.x) * (bx.w - bx.y);
    }
    __syncthreads();

    // ---- suppression rows: warp w handles i = w, w+32, ... ----
    int tmax = (ncand + 31) >> 5;
    for (int i = warp; i < ncand; i += 32) {
        float4 A  = sbox[i];
        float aar = sarea[i];
        unsigned long long myw = 0ull;
        for (int t = (i >> 5); t < tmax; t++) {
            int j = t * 32 + lane;
            bool hit = false;
            if (j > i && j < ncand) {
                float4 B = sbox[j];
                float lx = fmaxf(A.x, B.x);
                float ly = fmaxf(A.y, B.y);
                float rx = fminf(A.z, B.z);
                float ry = fminf(A.w, B.w);
                float iw = fmaxf(rx - lx, 0.0f);
                float ih = fmaxf(ry - ly, 0.0f);
                float inter = iw * ih;
                // iou > TH  <=>  inter > TH*(a+b-inter+eps)
                hit = inter > NMS_TH * (aar + sarea[j] - inter + 1e-9f);
            }
            unsigned bal = __ballot_sync(0xffffffffu, hit);
            if (lane == (t >> 1))
                myw |= ((unsigned long long)bal) << ((t & 1) * 32);
        }
        if (i < SROWS) srows[i * NW + lane] = myw;
        else           g_sup[b][i][lane]    = myw;   // rare overflow path
    }
    __syncthreads();

    // ---- serial greedy scan on warp 0, all-smem fast path ----
    if (warp == 0) {
        // cv[i] == (i < ncand): removal-mask init is pure arithmetic
        int start = lane * 64;
        unsigned long long remv =
            (ncand <= start) ? ~0ull
          : (ncand >= start + 64) ? 0ull
          : (~0ull << (ncand - start));

        int cnt = 0, i = 0;
        while (i < KTOP && cnt < NDET) {
            int w = i >> 6;
            unsigned long long rw    = __shfl_sync(0xffffffffu, remv, w);
            unsigned long long avail = ~rw & (~0ull << (i & 63));
            if (avail == 0ull) { i = (w + 1) << 6; continue; }
            int bit = __ffsll((long long)avail) - 1;
            i = (w << 6) | bit;
            if (lane == 0) kept[cnt] = i;
            cnt++;
            remv |= (i < SROWS) ? srows[i * NW + lane] : g_sup[b][i][lane];
            i++;
        }
        if (lane == 0) s_cnt = cnt;
    }
    __syncthreads();

    // ---- write outputs ----
    int cnt = s_cnt;
    for (int s = tid; s < NDET; s += 1024) {
        float b0 = 0.f, b1 = 0.f, b2 = 0.f, b3 = 0.f, sv = 0.f, lv = 0.f;
        if (s < cnt) {
            int k = kept[s];
            b0 = g_box[b][k][0]; b1 = g_box[b][k][1];
            b2 = g_box[b][k][2]; b3 = g_box[b][k][3];
            sv = g_val[b][k];
            lv = (float)g_lab[b][k];
        }
        float* ob = out + (size_t)b * NDET * 4 + s * 4;
        ob[0] = b0; ob[1] = b1; ob[2] = b2; ob[3] = b3;
        out[NIMG * NDET * 4 + b * NDET + s] = sv;
        out[NIMG * NDET * 5 + b * NDET + s] = lv;
    }
}

// ---------------- launcher ---------------------------------------------------
extern "C" void kernel_launch(void* const* d_in, const int* in_sizes, int n_in,
                              void* d_out, int out_size) {
    const float* logits = (const float*)d_in[0];   // [8,8000,81]
    const float* deltas = (const float*)d_in[1];   // [8,8000,324]
    const float* props  = (const float*)d_in[2];   // [8,8000,4]
    float* out = (float*)d_out;                    // [boxes|scores|labels] f32

    cudaFuncSetAttribute(supscan_kernel,
                         cudaFuncAttributeMaxDynamicSharedMemorySize,
                         SUPSCAN_SMEM);

    score_kernel<<<dim3(NPROP / 8, NIMG), 256>>>(logits, deltas, props);
    sortgather_kernel<<<NIMG, 1024>>>(deltas, props);
    supscan_kernel<<<NIMG, 1024, SUPSCAN_SMEM>>>(out);
}

// round 11
// speedup vs baseline: 1.4951x; 1.4951x over previous
#include <cuda_runtime.h>
#include <cstdint>

#define NIMG  8
#define NPROP 8000
#define NCLS  80
#define NLOG  81
#define KTOP  2048
#define CAP   4096
#define NDET  100
#define NW    32    // 2048 / 64 bits
#define SUPB  4     // sup blocks per image
#define SROWS 640   // suppression rows staged into scan smem

#define SCORE_THRE 0.15f
#define MIN_AREA   0.1f
#define NMS_TH     0.5f

#define SCAN_SMEM (SROWS * NW * 8)   // 163840 B dynamic smem for scan

// ---------------- scratch (device globals; no allocations allowed) ----------
__device__ int                 g_cnt[NIMG];
__device__ int                 g_ncand[NIMG];
__device__ unsigned long long  g_keys[NIMG][CAP];
__device__ float               g_box[NIMG][KTOP][4];
__device__ float               g_val[NIMG][KTOP];
__device__ int                 g_lab[NIMG][KTOP];
__device__ float               g_maxc[NIMG];
__device__ unsigned long long  g_sup[NIMG][KTOP][NW];

// ---------------- kernel 1: softmax + decode + filter + append --------------
// block = 8 warps = 8 proposals; logits staged via coalesced float4 -> smem
__global__ void score_kernel(const float* __restrict__ logits,
                             const float* __restrict__ deltas,
                             const float* __restrict__ props) {
    __shared__ float slg[8 * NLOG];              // 2592 B, 648 floats = 162 f4
    int b    = blockIdx.y;
    int p0   = blockIdx.x * 8;                   // first proposal of block
    int tid  = threadIdx.x;
    int wp   = tid >> 5;                         // proposal within block
    int lane = tid & 31;

    // stage 8 rows of logits (16B-aligned: 648 floats per block)
    const float4* src = (const float4*)(logits + (size_t)(b * NPROP + p0) * NLOG);
    if (tid < 162) ((float4*)slg)[tid] = src[tid];
    __syncthreads();

    int p = p0 + wp;
    const float* lg = slg + wp * NLOG;
    float v0 = lg[lane];
    float v1 = lg[32 + lane];
    float v2 = (lane < NLOG - 64) ? lg[64 + lane] : -3.4e38f;

    float mx = fmaxf(fmaxf(v0, v1), v2);
#pragma unroll
    for (int o = 16; o; o >>= 1) mx = fmaxf(mx, __shfl_xor_sync(0xffffffffu, mx, o));

    float e0 = expf(v0 - mx);
    float e1 = expf(v1 - mx);
    float e2 = (lane < NLOG - 64) ? expf(v2 - mx) : 0.0f;
    float s  = e0 + e1 + e2;
#pragma unroll
    for (int o = 16; o; o >>= 1) s += __shfl_xor_sync(0xffffffffu, s, o);

    float inv_s = (lane == 0) ? (1.0f / s) : 0.0f;   // one IEEE rcp per warp
    inv_s = __shfl_sync(0xffffffffu, inv_s, 0);

    const float* pr = props + (size_t)(b * NPROP + p) * 4;
    float wa = pr[2] - pr[0];
    float ha = pr[3] - pr[1];

    const float* dl = deltas + (size_t)(b * NPROP + p) * (4 * NLOG);

    float es[3] = { e0, e1, e2 };
#pragma unroll
    for (int t = 0; t < 3; t++) {
        int cls = lane + 32 * t;                 // softmax class index
        if (cls >= 1 && cls < NLOG) {
            float sc = es[t] * inv_s;
            if (sc > SCORE_THRE) {
                float dw = dl[4 * cls + 2];
                float dh = dl[4 * cls + 3];
                float w  = __expf(dw) * wa;      // area test only
                float h  = __expf(dh) * ha;
                float area = h * w;
                if (area > MIN_AREA) {
                    int idx = p * NCLS + (cls - 1);
                    int pos = atomicAdd(&g_cnt[b], 1);
                    if (pos < CAP) {
                        unsigned long long key =
                            ((unsigned long long)__float_as_uint(sc) << 32) |
                            (unsigned)(0xFFFFFFFFu - (unsigned)idx);
                        g_keys[b][pos] = key;
                    }
                }
            }
        }
    }
}

// ---------------- kernel 2: sort + gather fused (one block per image) -------
__global__ void sortgather_kernel(const float* __restrict__ deltas,
                                  const float* __restrict__ props) {
    __shared__ unsigned long long sk[CAP];
    __shared__ float smax[32];
    int b = blockIdx.x;
    int t = threadIdx.x;
    int cnt = g_cnt[b];
    if (cnt > CAP) cnt = CAP;

    int npow = 1024;
    while (npow < cnt) npow <<= 1;               // <= CAP

    for (int i = t; i < npow; i += 1024)
        sk[i] = (i < cnt) ? g_keys[b][i] : 0ull;
    __syncthreads();
    if (t == 0) {
        g_cnt[b]   = 0;                          // reset for next replay
        g_ncand[b] = (cnt < KTOP) ? cnt : KTOP;  // real candidate count
    }

    for (int k = 2; k <= npow; k <<= 1) {
        for (int j = k >> 1; j; j >>= 1) {
            for (int idx = t; idx < (npow >> 1); idx += 1024) {
                int low = idx & (j - 1);
                int i   = ((idx ^ low) << 1) | low;
                int ixj = i | j;
                unsigned long long a = sk[i], c = sk[ixj];
                bool up = ((i & k) == 0);
                if ((a > c) == up) { sk[i] = c; sk[ixj] = a; }
            }
            __syncthreads();
        }
    }

    // ---- gather phase: ranks r = t, t+1024 ----
    float m_loc = 0.0f;
#pragma unroll
    for (int rr = 0; rr < KTOP / 1024; rr++) {
        int r = t + rr * 1024;
        unsigned long long key = (r < npow) ? sk[npow - 1 - r] : 0ull;
        if (key == 0ull) {
            g_val[b][r] = -1.0f;
            g_lab[b][r] = 0;
            g_box[b][r][0] = 0.f; g_box[b][r][1] = 0.f;
            g_box[b][r][2] = 0.f; g_box[b][r][3] = 0.f;
        } else {
            float    sc  = __uint_as_float((unsigned)(key >> 32));
            unsigned idx = 0xFFFFFFFFu - (unsigned)(key & 0xFFFFFFFFull);
            int p   = (int)(idx / NCLS);
            int cls = (int)(idx - (unsigned)p * NCLS) + 1;

            const float* pr = props + (size_t)(b * NPROP + p) * 4;
            float ax0 = pr[0], ay0 = pr[1], ax1 = pr[2], ay1 = pr[3];
            float wa  = ax1 - ax0, ha = ay1 - ay0;
            float cxa = ax0 + 0.5f * wa, cya = ay0 + 0.5f * ha;

            const float* dl = deltas + (size_t)(b * NPROP + p) * (4 * NLOG);
            float dx = dl[4 * cls + 0];
            float dy = dl[4 * cls + 1];
            float dw = dl[4 * cls + 2];
            float dh = dl[4 * cls + 3];
            float cx = dx * wa + cxa;
            float cy = dy * ha + cya;
            float w  = expf(dw) * wa;
            float h  = expf(dh) * ha;
            float bx0 = cx - 0.5f * w, by0 = cy - 0.5f * h;
            float bx1 = cx + 0.5f * w, by1 = cy + 0.5f * h;

            g_box[b][r][0] = bx0; g_box[b][r][1] = by0;
            g_box[b][r][2] = bx1; g_box[b][r][3] = by1;
            g_val[b][r] = sc;
            g_lab[b][r] = cls;

            m_loc = fmaxf(m_loc, fmaxf(fmaxf(bx0, bx1), fmaxf(by0, by1)));
        }
    }

    // ---- block max reduction for max_coord ----
#pragma unroll
    for (int o = 16; o; o >>= 1)
        m_loc = fmaxf(m_loc, __shfl_xor_sync(0xffffffffu, m_loc, o));
    if ((t & 31) == 0) smax[t >> 5] = m_loc;
    __syncthreads();
    if (t < 32) {
        float m = smax[t];
#pragma unroll
        for (int o = 16; o; o >>= 1)
            m = fmaxf(m, __shfl_xor_sync(0xffffffffu, m, o));
        if (t == 0) g_maxc[b] = m;
    }
}

// ---------------- kernel 3: suppression bitmask, 4 blocks/image -------------
__global__ void sup_kernel() {
    __shared__ float4 sbox[KTOP];    // 32 KB
    __shared__ float  sarea[KTOP];   //  8 KB
    int b     = blockIdx.y;
    int q     = blockIdx.x;
    int ncand = g_ncand[b];
    float mc  = g_maxc[b] + 1.0f;

    for (int i = threadIdx.x; i < ncand; i += blockDim.x) {
        float4 bx = *(const float4*)&g_box[b][i][0];
        float off = (float)g_lab[b][i] * mc;
        bx.x += off; bx.y += off; bx.z += off; bx.w += off;
        sbox[i]  = bx;
        sarea[i] = (bx.z - bx.x) * (bx.w - bx.y);
    }
    __syncthreads();

    int warp = threadIdx.x >> 5;
    int lane = threadIdx.x & 31;
    int gw   = q * 32 + warp;                    // 0..127
    int tmax = (ncand + 31) >> 5;

    for (int i = gw; i < ncand; i += SUPB * 32) {
        float4 A  = sbox[i];
        float aar = sarea[i];
        unsigned long long myw = 0ull;
        for (int t = (i >> 5); t < tmax; t++) {
            int j = t * 32 + lane;
            bool hit = false;
            if (j > i && j < ncand) {
                float4 B = sbox[j];
                float lx = fmaxf(A.x, B.x);
                float ly = fmaxf(A.y, B.y);
                float rx = fminf(A.z, B.z);
                float ry = fminf(A.w, B.w);
                float iw = fmaxf(rx - lx, 0.0f);
                float ih = fmaxf(ry - ly, 0.0f);
                float inter = iw * ih;
                // iou > TH  <=>  inter > TH*(a+b-inter+eps)
                hit = inter > NMS_TH * (aar + sarea[j] - inter + 1e-9f);
            }
            unsigned bal = __ballot_sync(0xffffffffu, hit);
            if (lane == (t >> 1))
                myw |= ((unsigned long long)bal) << ((t & 1) * 32);
        }
        g_sup[b][i][lane] = myw;                 // full 256B row overwrite
    }
}

// ---------------- kernel 4: greedy NMS, all rows staged to smem -------------
// 1024 threads/image: cooperative f4 stage of <=SROWS rows, chain on warp 0
__global__ void scan_kernel(float* __restrict__ out) {
    extern __shared__ unsigned long long srows[];   // SROWS * NW
    __shared__ int kept[NDET];
    __shared__ int s_cnt;
    int b    = blockIdx.x;
    int tid  = threadIdx.x;
    int warp = tid >> 5;
    int lane = tid & 31;
    int ncand = g_ncand[b];

    // stage suppression rows [0, min(ncand, SROWS)) as float4
    int rows = (ncand < SROWS) ? ncand : SROWS;
    const float4* src = (const float4*)&g_sup[b][0][0];
    float4* dst = (float4*)srows;
    for (int i = tid; i < rows * 16; i += 1024) dst[i] = src[i];
    __syncthreads();

    if (warp == 0) {
        // cv[i] == (i < ncand): removal-mask init is pure arithmetic
        int start = lane * 64;
        unsigned long long remv =
            (ncand <= start) ? ~0ull
          : (ncand >= start + 64) ? 0ull
          : (~0ull << (ncand - start));

        int cnt = 0, i = 0;
        while (i < KTOP && cnt < NDET) {
            int w = i >> 6;
            unsigned long long rw    = __shfl_sync(0xffffffffu, remv, w);
            unsigned long long avail = ~rw & (~0ull << (i & 63));
            if (avail == 0ull) { i = (w + 1) << 6; continue; }
            int bit = __ffsll((long long)avail) - 1;
            i = (w << 6) | bit;
            if (lane == 0) kept[cnt] = i;
            cnt++;
            remv |= (i < SROWS) ? srows[i * NW + lane] : g_sup[b][i][lane];
            i++;
        }
        if (lane == 0) s_cnt = cnt;
    }
    __syncthreads();

    int cnt = s_cnt;
    for (int s = tid; s < NDET; s += 1024) {
        float b0 = 0.f, b1 = 0.f, b2 = 0.f, b3 = 0.f, sv = 0.f, lv = 0.f;
        if (s < cnt) {
            int k = kept[s];
            b0 = g_box[b][k][0]; b1 = g_box[b][k][1];
            b2 = g_box[b][k][2]; b3 = g_box[b][k][3];
            sv = g_val[b][k];
            lv = (float)g_lab[b][k];
        }
        float* ob = out + (size_t)b * NDET * 4 + s * 4;
        ob[0] = b0; ob[1] = b1; ob[2] = b2; ob[3] = b3;
        out[NIMG * NDET * 4 + b * NDET + s] = sv;
        out[NIMG * NDET * 5 + b * NDET + s] = lv;
    }
}

// ---------------- launcher ---------------------------------------------------
extern "C" void kernel_launch(void* const* d_in, const int* in_sizes, int n_in,
                              void* d_out, int out_size) {
    const float* logits = (const float*)d_in[0];   // [8,8000,81]
    const float* deltas = (const float*)d_in[1];   // [8,8000,324]
    const float* props  = (const float*)d_in[2];   // [8,8000,4]
    float* out = (float*)d_out;                    // [boxes|scores|labels] f32

    cudaFuncSetAttribute(scan_kernel,
                         cudaFuncAttributeMaxDynamicSharedMemorySize,
                         SCAN_SMEM);

    score_kernel<<<dim3(NPROP / 8, NIMG), 256>>>(logits, deltas, props);
    sortgather_kernel<<<NIMG, 1024>>>(deltas, props);
    sup_kernel<<<dim3(SUPB, NIMG), 1024>>>();
    scan_kernel<<<NIMG, 1024, SCAN_SMEM>>>(out);
}

// round 14
// speedup vs baseline: 1.5211x; 1.0174x over previous
#include <cuda_runtime.h>
#include <cstdint>

#define NIMG  8
#define NPROP 8000
#define NCLS  80
#define NLOG  81
#define KTOP  2048
#define CAP   4096
#define NDET  100
#define NW    32    // 2048 / 64 bits
#define SUPB  4     // sup blocks per image
#define SROWS 640   // suppression rows staged into scan smem

#define SCORE_THRE 0.15f
#define MIN_AREA   0.1f
#define NMS_TH     0.5f

#define SCAN_SMEM (SROWS * NW * 8)   // 163840 B dynamic smem for scan

// ---------------- scratch (device globals; no allocations allowed) ----------
__device__ int                 g_cnt[NIMG];
__device__ int                 g_ncand[NIMG];
__device__ unsigned long long  g_keys[NIMG][CAP];
__device__ float               g_box[NIMG][KTOP][4];
__device__ float               g_val[NIMG][KTOP];
__device__ int                 g_lab[NIMG][KTOP];
__device__ float               g_maxc[NIMG];
__device__ unsigned long long  g_sup[NIMG][KTOP][NW];

// ---------------- kernel 1: softmax + decode + filter + append --------------
// block = 8 warps = 8 proposals; logits staged via coalesced float4 -> smem
__global__ void score_kernel(const float* __restrict__ logits,
                             const float* __restrict__ deltas,
                             const float* __restrict__ props) {
    __shared__ float slg[8 * NLOG];              // 2592 B, 648 floats = 162 f4
    int b    = blockIdx.y;
    int p0   = blockIdx.x * 8;                   // first proposal of block
    int tid  = threadIdx.x;
    int wp   = tid >> 5;                         // proposal within block
    int lane = tid & 31;

    // stage 8 rows of logits (16B-aligned: 648 floats per block)
    const float4* src = (const float4*)(logits + (size_t)(b * NPROP + p0) * NLOG);
    if (tid < 162) ((float4*)slg)[tid] = src[tid];
    __syncthreads();

    int p = p0 + wp;
    const float* lg = slg + wp * NLOG;
    float v0 = lg[lane];
    float v1 = lg[32 + lane];
    float v2 = (lane < NLOG - 64) ? lg[64 + lane] : -3.4e38f;

    float mx = fmaxf(fmaxf(v0, v1), v2);
#pragma unroll
    for (int o = 16; o; o >>= 1) mx = fmaxf(mx, __shfl_xor_sync(0xffffffffu, mx, o));

    float e0 = expf(v0 - mx);
    float e1 = expf(v1 - mx);
    float e2 = (lane < NLOG - 64) ? expf(v2 - mx) : 0.0f;
    float s  = e0 + e1 + e2;
#pragma unroll
    for (int o = 16; o; o >>= 1) s += __shfl_xor_sync(0xffffffffu, s, o);

    float inv_s = (lane == 0) ? (1.0f / s) : 0.0f;   // one IEEE rcp per warp
    inv_s = __shfl_sync(0xffffffffu, inv_s, 0);

    const float* pr = props + (size_t)(b * NPROP + p) * 4;
    float wa = pr[2] - pr[0];
    float ha = pr[3] - pr[1];

    const float* dl = deltas + (size_t)(b * NPROP + p) * (4 * NLOG);

    float es[3] = { e0, e1, e2 };
#pragma unroll
    for (int t = 0; t < 3; t++) {
        int cls = lane + 32 * t;                 // softmax class index
        if (cls >= 1 && cls < NLOG) {
            float sc = es[t] * inv_s;
            if (sc > SCORE_THRE) {
                float dw = dl[4 * cls + 2];
                float dh = dl[4 * cls + 3];
                float w  = __expf(dw) * wa;      // area test only
                float h  = __expf(dh) * ha;
                float area = h * w;
                if (area > MIN_AREA) {
                    int idx = p * NCLS + (cls - 1);
                    int pos = atomicAdd(&g_cnt[b], 1);
                    if (pos < CAP) {
                        unsigned long long key =
                            ((unsigned long long)__float_as_uint(sc) << 32) |
                            (unsigned)(0xFFFFFFFFu - (unsigned)idx);
                        g_keys[b][pos] = key;
                    }
                }
            }
        }
    }
}

// ---------------- kernel 2: sort + gather fused (one block per image) -------
__global__ void sortgather_kernel(const float* __restrict__ deltas,
                                  const float* __restrict__ props) {
    __shared__ unsigned long long sk[CAP];
    __shared__ float smax[32];
    int b = blockIdx.x;
    int t = threadIdx.x;
    int cnt = g_cnt[b];
    if (cnt > CAP) cnt = CAP;

    int npow = 1024;
    while (npow < cnt) npow <<= 1;               // <= CAP

    for (int i = t; i < npow; i += 1024)
        sk[i] = (i < cnt) ? g_keys[b][i] : 0ull;
    __syncthreads();
    if (t == 0) {
        g_cnt[b]   = 0;                          // reset for next replay
        g_ncand[b] = (cnt < KTOP) ? cnt : KTOP;  // real candidate count
    }

    for (int k = 2; k <= npow; k <<= 1) {
        for (int j = k >> 1; j; j >>= 1) {
            for (int idx = t; idx < (npow >> 1); idx += 1024) {
                int low = idx & (j - 1);
                int i   = ((idx ^ low) << 1) | low;
                int ixj = i | j;
                unsigned long long a = sk[i], c = sk[ixj];
                bool up = ((i & k) == 0);
                if ((a > c) == up) { sk[i] = c; sk[ixj] = a; }
            }
            __syncthreads();
        }
    }

    // ---- gather phase: ranks r = t, t+1024 ----
    float m_loc = 0.0f;
#pragma unroll
    for (int rr = 0; rr < KTOP / 1024; rr++) {
        int r = t + rr * 1024;
        unsigned long long key = (r < npow) ? sk[npow - 1 - r] : 0ull;
        if (key == 0ull) {
            g_val[b][r] = -1.0f;
            g_lab[b][r] = 0;
            g_box[b][r][0] = 0.f; g_box[b][r][1] = 0.f;
            g_box[b][r][2] = 0.f; g_box[b][r][3] = 0.f;
        } else {
            float    sc  = __uint_as_float((unsigned)(key >> 32));
            unsigned idx = 0xFFFFFFFFu - (unsigned)(key & 0xFFFFFFFFull);
            int p   = (int)(idx / NCLS);
            int cls = (int)(idx - (unsigned)p * NCLS) + 1;

            const float* pr = props + (size_t)(b * NPROP + p) * 4;
            float ax0 = pr[0], ay0 = pr[1], ax1 = pr[2], ay1 = pr[3];
            float wa  = ax1 - ax0, ha = ay1 - ay0;
            float cxa = ax0 + 0.5f * wa, cya = ay0 + 0.5f * ha;

            const float* dl = deltas + (size_t)(b * NPROP + p) * (4 * NLOG);
            float dx = dl[4 * cls + 0];
            float dy = dl[4 * cls + 1];
            float dw = dl[4 * cls + 2];
            float dh = dl[4 * cls + 3];
            float cx = dx * wa + cxa;
            float cy = dy * ha + cya;
            float w  = expf(dw) * wa;
            float h  = expf(dh) * ha;
            float bx0 = cx - 0.5f * w, by0 = cy - 0.5f * h;
            float bx1 = cx + 0.5f * w, by1 = cy + 0.5f * h;

            g_box[b][r][0] = bx0; g_box[b][r][1] = by0;
            g_box[b][r][2] = bx1; g_box[b][r][3] = by1;
            g_val[b][r] = sc;
            g_lab[b][r] = cls;

            m_loc = fmaxf(m_loc, fmaxf(fmaxf(bx0, bx1), fmaxf(by0, by1)));
        }
    }

    // ---- block max reduction for max_coord ----
#pragma unroll
    for (int o = 16; o; o >>= 1)
        m_loc = fmaxf(m_loc, __shfl_xor_sync(0xffffffffu, m_loc, o));
    if ((t & 31) == 0) smax[t >> 5] = m_loc;
    __syncthreads();
    if (t < 32) {
        float m = smax[t];
#pragma unroll
        for (int o = 16; o; o >>= 1)
            m = fmaxf(m, __shfl_xor_sync(0xffffffffu, m, o));
        if (t == 0) g_maxc[b] = m;
    }
}

// ---------------- kernel 3: suppression bitmask, 4 blocks/image -------------
__global__ void sup_kernel() {
    __shared__ float4 sbox[KTOP];    // 32 KB
    __shared__ float  sarea[KTOP];   //  8 KB
    int b     = blockIdx.y;
    int q     = blockIdx.x;
    int ncand = g_ncand[b];
    float mc  = g_maxc[b] + 1.0f;

    for (int i = threadIdx.x; i < ncand; i += blockDim.x) {
        float4 bx = *(const float4*)&g_box[b][i][0];
        float off = (float)g_lab[b][i] * mc;
        bx.x += off; bx.y += off; bx.z += off; bx.w += off;
        sbox[i]  = bx;
        sarea[i] = (bx.z - bx.x) * (bx.w - bx.y);
    }
    __syncthreads();

    int warp = threadIdx.x >> 5;
    int lane = threadIdx.x & 31;
    int gw   = q * 32 + warp;                    // 0..127
    int tmax = (ncand + 31) >> 5;

    for (int i = gw; i < ncand; i += SUPB * 32) {
        float4 A  = sbox[i];
        float aar = sarea[i];
        unsigned long long myw = 0ull;
        for (int t = (i >> 5); t < tmax; t++) {
            int j = t * 32 + lane;
            bool hit = false;
            if (j > i && j < ncand) {
                float4 B = sbox[j];
                float lx = fmaxf(A.x, B.x);
                float ly = fmaxf(A.y, B.y);
                float rx = fminf(A.z, B.z);
                float ry = fminf(A.w, B.w);
                float iw = fmaxf(rx - lx, 0.0f);
                float ih = fmaxf(ry - ly, 0.0f);
                float inter = iw * ih;
                // iou > TH  <=>  inter > TH*(a+b-inter+eps)
                hit = inter > NMS_TH * (aar + sarea[j] - inter + 1e-9f);
            }
            unsigned bal = __ballot_sync(0xffffffffu, hit);
            if (lane == (t >> 1))
                myw |= ((unsigned long long)bal) << ((t & 1) * 32);
        }
        g_sup[b][i][lane] = myw;                 // full 256B row overwrite
    }
}

// ---------------- kernel 4: greedy NMS, shfl-free steady-state chain --------
// 1024 threads/image: cooperative f4 stage of <=SROWS rows; warp 0 runs chain.
// Per-step: dual LDS (own word + broadcast of current word) — no shfl except
// at 64-bit word boundaries (~10 total).
__global__ void scan_kernel(float* __restrict__ out) {
    extern __shared__ unsigned long long srows[];   // SROWS * NW
    __shared__ int kept[NDET];
    __shared__ int s_cnt;
    int b    = blockIdx.x;
    int tid  = threadIdx.x;
    int warp = tid >> 5;
    int lane = tid & 31;
    int ncand = g_ncand[b];

    // stage suppression rows [0, min(ncand, SROWS)) as float4
    int rows = (ncand < SROWS) ? ncand : SROWS;
    const float4* src = (const float4*)&g_sup[b][0][0];
    float4* dst = (float4*)srows;
    for (int i = tid; i < rows * 16; i += 1024) dst[i] = src[i];
    __syncthreads();

    if (warp == 0) {
        // cv[i] == (i < ncand): removal-mask init is pure arithmetic
        int start = lane * 64;
        unsigned long long remv =
            (ncand <= start) ? ~0ull
          : (ncand >= start + 64) ? 0ull
          : (~0ull << (ncand - start));

        int cnt = 0;
        int w   = 0;
        unsigned long long rw    = __shfl_sync(0xffffffffu, remv, 0);
        unsigned long long avail = ~rw;
        while (cnt < NDET) {
            if (avail == 0ull) {                 // advance to next word
                w++;
                if (w >= NW) break;
                rw    = __shfl_sync(0xffffffffu, remv, w);
                avail = ~rw;
                continue;
            }
            int bit = __ffsll((long long)avail) - 1;
            int i   = (w << 6) | bit;
            if (lane == 0) kept[cnt] = i;
            cnt++;
            unsigned long long row, roww;
            if (i < SROWS) {
                row  = srows[i * NW + lane];     // own word (per-lane)
                roww = srows[i * NW + w];        // broadcast: current word
            } else {
                row  = g_sup[b][i][lane];
                roww = g_sup[b][i][w];
            }
            remv |= row;                         // keeps all lanes current
            rw   |= roww;                        // local copy of word w
            avail = (bit == 63) ? 0ull
                                : (~rw & (~0ull << (bit + 1)));
        }
        if (lane == 0) s_cnt = cnt;
    }
    __syncthreads();

    int cnt = s_cnt;
    for (int s = tid; s < NDET; s += 1024) {
        float b0 = 0.f, b1 = 0.f, b2 = 0.f, b3 = 0.f, sv = 0.f, lv = 0.f;
        if (s < cnt) {
            int k = kept[s];
            b0 = g_box[b][k][0]; b1 = g_box[b][k][1];
            b2 = g_box[b][k][2]; b3 = g_box[b][k][3];
            sv = g_val[b][k];
            lv = (float)g_lab[b][k];
        }
        float* ob = out + (size_t)b * NDET * 4 + s * 4;
        ob[0] = b0; ob[1] = b1; ob[2] = b2; ob[3] = b3;
        out[NIMG * NDET * 4 + b * NDET + s] = sv;
        out[NIMG * NDET * 5 + b * NDET + s] = lv;
    }
}

// ---------------- launcher ---------------------------------------------------
extern "C" void kernel_launch(void* const* d_in, const int* in_sizes, int n_in,
                              void* d_out, int out_size) {
    const float* logits = (const float*)d_in[0];   // [8,8000,81]
    const float* deltas = (const float*)d_in[1];   // [8,8000,324]
    const float* props  = (const float*)d_in[2];   // [8,8000,4]
    float* out = (float*)d_out;                    // [boxes|scores|labels] f32

    cudaFuncSetAttribute(scan_kernel,
                         cudaFuncAttributeMaxDynamicSharedMemorySize,
                         SCAN_SMEM);

    score_kernel<<<dim3(NPROP / 8, NIMG), 256>>>(logits, deltas, props);
    sortgather_kernel<<<NIMG, 1024>>>(deltas, props);
    sup_kernel<<<dim3(SUPB, NIMG), 1024>>>();
    scan_kernel<<<NIMG, 1024, SCAN_SMEM>>>(out);
}